// round 13
// baseline (speedup 1.0000x reference)
#include <cuda_runtime.h>
#include <cuda_fp16.h>
#include <cuda_bf16.h>

// ---------------------------------------------------------------------------
// SimpleFineGrainedHead4: B=128, Q=128, T=64, V=196, D=768, E=512
// Output layout (fp32, 17195008 elems):
//   [0]        visual_embed_cls  [128,512]
//   [65536]    textual_embed_cls [128,512]
//   [131072]   ve                [128,196,512]
//   [12976128] te                [128,64,512]
//   [17170432] text_mask         [128,64]
//   [17178624] sim               [128,128]
// NOTE: this harness targets compute_103 (no 'a'), so tcgen05 is unavailable;
// everything runs on legacy mma.sync HMMA + cp.async.
// ---------------------------------------------------------------------------

#define DEVFN __device__ __forceinline__

// fp16 copies of normalized ve/te for the MaxSim stage (device scratch).
__device__ __half g_ve_h[25088 * 512];
__device__ __half g_te_h[8192 * 512];

// fp16 h/r copies of projection inputs (A: 33536 rows x 768) and weights.
__device__ __half g_Ah[33536 * 768];
__device__ __half g_Ar[33536 * 768];
__device__ __half g_Wh[4 * 512 * 768];

// ---------------- PTX helpers ----------------------------------------------
DEVFN unsigned smem_u32(const void* p) {
    return (unsigned)__cvta_generic_to_shared((void*)p);
}
DEVFN void ldsm4(unsigned& r0, unsigned& r1, unsigned& r2, unsigned& r3, const void* p) {
    unsigned a = smem_u32(p);
    asm volatile("ldmatrix.sync.aligned.m8n8.x4.shared.b16 {%0,%1,%2,%3}, [%4];\n"
                 : "=r"(r0), "=r"(r1), "=r"(r2), "=r"(r3) : "r"(a));
}
DEVFN void mma16816(float* c, unsigned a0, unsigned a1, unsigned a2, unsigned a3,
                    unsigned b0, unsigned b1) {
    asm volatile("mma.sync.aligned.m16n8k16.row.col.f32.f16.f16.f32 "
                 "{%0,%1,%2,%3}, {%4,%5,%6,%7}, {%8,%9}, {%0,%1,%2,%3};\n"
                 : "+f"(c[0]), "+f"(c[1]), "+f"(c[2]), "+f"(c[3])
                 : "r"(a0), "r"(a1), "r"(a2), "r"(a3), "r"(b0), "r"(b1));
}
DEVFN void cp16(void* dst, const void* src) {
    unsigned d = smem_u32(dst);
    asm volatile("cp.async.cg.shared.global [%0], [%1], 16;\n" :: "r"(d), "l"(src));
}
DEVFN void cp_commit() { asm volatile("cp.async.commit_group;\n"); }
DEVFN void cp_wait0()  { asm volatile("cp.async.wait_group 0;\n"); }
DEVFN void cp_wait1()  { asm volatile("cp.async.wait_group 1;\n"); }

// order-preserving float <-> uint encoding (for atomicMax on floats)
DEVFN unsigned fenc(float f) {
    unsigned u = __float_as_uint(f);
    return (u & 0x80000000u) ? ~u : (u | 0x80000000u);
}
DEVFN float fdec(unsigned u) {
    return __uint_as_float((u & 0x80000000u) ? (u & 0x7fffffffu) : ~u);
}

// ---------------------------------------------------------------------------
// Conversion kernels: fp32 -> fp16 (h) and residual (r = fp16(x - h)).
// ---------------------------------------------------------------------------
__global__ void __launch_bounds__(256) convA_kernel(
    const float* __restrict__ src, __half* __restrict__ h,
    __half* __restrict__ r, int n4) {
    for (int i = blockIdx.x * blockDim.x + threadIdx.x; i < n4;
         i += gridDim.x * blockDim.x) {
        float4 v = ((const float4*)src)[i];
        float x[4] = {v.x, v.y, v.z, v.w};
        __half hb[4], rb[4];
#pragma unroll
        for (int j = 0; j < 4; j++) {
            __half hh = __float2half_rn(x[j]);
            hb[j] = hh;
            rb[j] = __float2half_rn(x[j] - __half2float(hh));
        }
        ((uint2*)h)[i] = *(const uint2*)hb;
        ((uint2*)r)[i] = *(const uint2*)rb;
    }
}

__global__ void __launch_bounds__(256) convW_kernel(
    const float* __restrict__ src, __half* __restrict__ h, int n4) {
    for (int i = blockIdx.x * blockDim.x + threadIdx.x; i < n4;
         i += gridDim.x * blockDim.x) {
        float4 v = ((const float4*)src)[i];
        float x[4] = {v.x, v.y, v.z, v.w};
        __half hb[4];
#pragma unroll
        for (int j = 0; j < 4; j++) hb[j] = __float2half_rn(x[j]);
        ((uint2*)h)[i] = *(const uint2*)hb;
    }
}

// ---------------------------------------------------------------------------
// Projection GEMM v2 (pure fp16 operands, fp32 accum):
//   C[M,512] = (Ah+Ar)[M,768] @ Wh[512,768]^T + bias
// Tile BM=64, BN=64, BK=64, double-buffered cp.async. 256 threads = 8 warps
// (4M x 2N), warp tile 16x32. grid = (M/64, 8).
// ---------------------------------------------------------------------------
#define PKS 72  // smem K stride (halves)

__global__ void __launch_bounds__(256) proj2_kernel(
    int a_row0, const __half* __restrict__ Wh,
    const float* __restrict__ bias, float* __restrict__ C) {
    extern __shared__ __align__(16) __half smp[];
    __half (*tl)[3][64][PKS] = (__half(*)[3][64][PKS])smp;

    const int tid = threadIdx.x, warp = tid >> 5, lane = tid & 31;
    const int m0 = (warp & 3) * 16, n0w = (warp >> 2) * 32;

    const __half* Ah_g = g_Ah + (size_t)(a_row0 + blockIdx.x * 64) * 768;
    const __half* Ar_g = g_Ar + (size_t)(a_row0 + blockIdx.x * 64) * 768;
    const __half* Wh_g = Wh + (size_t)(blockIdx.y * 64) * 768;

    float acc[4][4];
#pragma unroll
    for (int i = 0; i < 4; i++)
#pragma unroll
        for (int j = 0; j < 4; j++) acc[i][j] = 0.f;

    for (int i = tid; i < 1536; i += 256) {
        int t = i >> 9, r = (i >> 3) & 63, c = (i & 7) * 8;
        const __half* src = (t == 0 ? Ah_g : (t == 1 ? Ar_g : Wh_g)) +
                            (size_t)r * 768 + c;
        cp16(&tl[0][t][r][c], src);
    }
    cp_commit();

    int buf = 0;
    for (int it = 0; it < 12; it++) {
        if (it < 11) {
            const int kb = (it + 1) * 64;
            const int ob = buf ^ 1;
            for (int i = tid; i < 1536; i += 256) {
                int t = i >> 9, r = (i >> 3) & 63, c = (i & 7) * 8;
                const __half* src = (t == 0 ? Ah_g : (t == 1 ? Ar_g : Wh_g)) +
                                    (size_t)r * 768 + kb + c;
                cp16(&tl[ob][t][r][c], src);
            }
            cp_commit();
            cp_wait1();
        } else {
            cp_wait0();
        }
        __syncthreads();

        const int alo = lane & 15, ahi = (lane >> 4) << 3;
#pragma unroll
        for (int ks = 0; ks < 4; ks++) {
            const int kk = ks * 16;
            unsigned ah0, ah1, ah2, ah3, ar0, ar1, ar2, ar3;
            ldsm4(ah0, ah1, ah2, ah3, &tl[buf][0][m0 + alo][kk + ahi]);
            ldsm4(ar0, ar1, ar2, ar3, &tl[buf][1][m0 + alo][kk + ahi]);
#pragma unroll
            for (int ntp = 0; ntp < 2; ntp++) {
                unsigned bh0, bh1, bh2, bh3;
                ldsm4(bh0, bh1, bh2, bh3,
                      &tl[buf][2][n0w + ntp * 16 + alo][kk + ahi]);
                mma16816(acc[2 * ntp],     ah0, ah1, ah2, ah3, bh0, bh2);
                mma16816(acc[2 * ntp],     ar0, ar1, ar2, ar3, bh0, bh2);
                mma16816(acc[2 * ntp + 1], ah0, ah1, ah2, ah3, bh1, bh3);
                mma16816(acc[2 * ntp + 1], ar0, ar1, ar2, ar3, bh1, bh3);
            }
        }
        __syncthreads();
        buf ^= 1;
    }

    const int g = lane >> 2, c2 = (lane & 3) * 2;
    const size_t r0 = blockIdx.x * 64 + m0 + g;
#pragma unroll
    for (int nt = 0; nt < 4; nt++) {
        int col = blockIdx.y * 64 + n0w + nt * 8 + c2;
        float b0 = bias[col], b1 = bias[col + 1];
        C[r0 * 512 + col]           = acc[nt][0] + b0;
        C[r0 * 512 + col + 1]       = acc[nt][1] + b1;
        C[(r0 + 8) * 512 + col]     = acc[nt][2] + b0;
        C[(r0 + 8) * 512 + col + 1] = acc[nt][3] + b1;
    }
}

// ---------------------------------------------------------------------------
// Row-wise L2 normalize (rows of 512 fp32), in place; also write fp16 copy.
// ---------------------------------------------------------------------------
__global__ void __launch_bounds__(256) norm_kernel(float* __restrict__ data,
                                                   int rows, int which) {
    __half* hout = which ? g_te_h : g_ve_h;
    const int row = blockIdx.x * 8 + (threadIdx.x >> 5);
    const int lane = threadIdx.x & 31;
    if (row >= rows) return;
    float* p = data + (size_t)row * 512;

    float4 v[4];
    float s = 0.f;
#pragma unroll
    for (int i = 0; i < 4; i++) {
        v[i] = *(const float4*)(p + i * 128 + lane * 4);
        s += v[i].x * v[i].x + v[i].y * v[i].y + v[i].z * v[i].z + v[i].w * v[i].w;
    }
#pragma unroll
    for (int o = 16; o; o >>= 1) s += __shfl_xor_sync(0xffffffffu, s, o);
    float inv = 1.0f / fmaxf(sqrtf(s), 1e-12f);

    __half* hp = hout + (size_t)row * 512;
#pragma unroll
    for (int i = 0; i < 4; i++) {
        float4 w = v[i];
        w.x *= inv; w.y *= inv; w.z *= inv; w.w *= inv;
        *(float4*)(p + i * 128 + lane * 4) = w;
        __half h[4] = {__float2half_rn(w.x), __float2half_rn(w.y),
                       __float2half_rn(w.z), __float2half_rn(w.w)};
        *(uint2*)(hp + i * 128 + lane * 4) = *(const uint2*)h;
    }
}

// ---------------------------------------------------------------------------
// text_mask[b][t] = (t < text_length[b]); detects int64 vs int32 storage.
// ---------------------------------------------------------------------------
__global__ void mask_kernel(const int* __restrict__ tl, float* __restrict__ mask) {
    const bool is64 = (tl[1] == 0);
    for (int i = blockIdx.x * blockDim.x + threadIdx.x; i < 128 * 64;
         i += gridDim.x * blockDim.x) {
        int b = i >> 6, t = i & 63;
        int len = is64 ? tl[2 * b] : tl[b];
        mask[i] = (t < len) ? 1.0f : 0.0f;
    }
}

// ---------------------------------------------------------------------------
// MaxSim v5. grid=(128 q, 32 b-quads), 512 thr = 16 warps (4M x 4N),
// warp tile 64(M) x 32(N). te for 4 b's (256 rows) and ve streamed through
// double-buffered K=64 smem tiles. V chunks {128, 96} (pad to 224; padded
// rows zeroed / masked). Each M-warp's 64 rows = exactly one b, so the
// col-max (over t within b) stays warp-local. 1 CTA/SM (115 KB smem).
// ---------------------------------------------------------------------------
#define KT  64   // K-tile halves
#define KTS 72   // smem K stride (halves)

__global__ void __launch_bounds__(512, 1) maxsim_kernel(float* __restrict__ sim) {
    const int q = blockIdx.x, bq = blockIdx.y;
    extern __shared__ char sm[];
    __half (*te_t)[256][KTS] = (__half(*)[256][KTS])sm;               // [2][256][KTS]
    __half (*ve_t)[128][KTS] = (__half(*)[128][KTS])(sm + 2 * 256 * KTS * 2);
    unsigned* rowmax = (unsigned*)(sm + (2 * 256 + 2 * 128) * KTS * 2); // [256]
    unsigned* colmax = rowmax + 256;                                    // [4][224]

    const int tid = threadIdx.x, warp = tid >> 5, lane = tid & 31;
    const int mw = warp >> 2, nw = warp & 3;   // 4 M-warps x 4 N-warps
    const int m0w = mw * 64, n0w = nw * 32;
    const int lrow = lane & 15, lcol = (lane >> 4) << 3;

    for (int i = tid; i < 256 + 896; i += 512) rowmax[i] = 0u;

    const __half* teb = g_te_h + (size_t)bq * 256 * 512;
    const __half* veq = g_ve_h + (size_t)q * 196 * 512;

    // ---- preload (chunk0, kt0) into buf 0 ----
    {
        for (int i = tid; i < 2048; i += 512) {
            int r = i >> 3, c = (i & 7) * 8;
            cp16(&te_t[0][r][c], teb + (size_t)r * 512 + c);
        }
        for (int i = tid; i < 1024; i += 512) {
            int r = i >> 3, c = (i & 7) * 8;
            cp16(&ve_t[0][r][c], veq + (size_t)r * 512 + c);
        }
        cp_commit();
    }

    float acc[4][4][4];
    int buf = 0;

    for (int it = 0; it < 16; it++) {
        const int chunk = it >> 3, kt = it & 7;
        if (kt == 0) {
#pragma unroll
            for (int a = 0; a < 4; a++)
#pragma unroll
                for (int b = 0; b < 4; b++)
#pragma unroll
                    for (int c = 0; c < 4; c++) acc[a][b][c] = 0.f;
        }

        // prefetch next K-tile into the other buffer
        const int nit = it + 1;
        if (nit < 16) {
            const int nch = nit >> 3, nkt = nit & 7;
            const int kb = nkt * KT;
            const int ob = buf ^ 1;
            for (int i = tid; i < 2048; i += 512) {
                int r = i >> 3, c = (i & 7) * 8;
                cp16(&te_t[ob][r][c], teb + (size_t)r * 512 + kb + c);
            }
            const int nrows = nch ? 96 : 128;
            const int vb0 = nch * 128;
            for (int i = tid; i < nrows * 8; i += 512) {
                int r = i >> 3, c = (i & 7) * 8;
                int v = vb0 + r;
                if (v < 196) cp16(&ve_t[ob][r][c], veq + (size_t)v * 512 + kb + c);
                else *(uint4*)&ve_t[ob][r][c] = make_uint4(0, 0, 0, 0);
            }
            cp_commit();
            cp_wait1();
        } else {
            cp_wait0();
        }
        __syncthreads();

        const bool active = !(chunk == 1 && nw == 3);
        if (active) {
#pragma unroll
            for (int k0 = 0; k0 < KT; k0 += 16) {
                unsigned a[4][4];
#pragma unroll
                for (int mt = 0; mt < 4; mt++)
                    ldsm4(a[mt][0], a[mt][1], a[mt][2], a[mt][3],
                          &te_t[buf][m0w + mt * 16 + lrow][k0 + lcol]);
                unsigned bb[2][4];
#pragma unroll
                for (int np = 0; np < 2; np++)
                    ldsm4(bb[np][0], bb[np][1], bb[np][2], bb[np][3],
                          &ve_t[buf][n0w + np * 16 + lrow][k0 + lcol]);
#pragma unroll
                for (int mt = 0; mt < 4; mt++) {
                    mma16816(acc[mt][0], a[mt][0], a[mt][1], a[mt][2], a[mt][3],
                             bb[0][0], bb[0][2]);
                    mma16816(acc[mt][1], a[mt][0], a[mt][1], a[mt][2], a[mt][3],
                             bb[0][1], bb[0][3]);
                    mma16816(acc[mt][2], a[mt][0], a[mt][1], a[mt][2], a[mt][3],
                             bb[1][0], bb[1][2]);
                    mma16816(acc[mt][3], a[mt][0], a[mt][1], a[mt][2], a[mt][3],
                             bb[1][1], bb[1][3]);
                }
            }

            // ---- end-of-chunk reductions ----
            if (kt == 7) {
                const int g = lane >> 2, c2 = (lane & 3) * 2;
                const int vbase = chunk * 128 + n0w;
                // row maxes (max over this chunk's v), mask v >= 196
#pragma unroll
                for (int mt = 0; mt < 4; mt++) {
                    float rA = -1e30f, rB = -1e30f;
#pragma unroll
                    for (int nt = 0; nt < 4; nt++) {
                        const int vb = vbase + nt * 8 + c2;
                        float x0 = (vb < 196)     ? acc[mt][nt][0] : -1e30f;
                        float x1 = (vb + 1 < 196) ? acc[mt][nt][1] : -1e30f;
                        float x2 = (vb < 196)     ? acc[mt][nt][2] : -1e30f;
                        float x3 = (vb + 1 < 196) ? acc[mt][nt][3] : -1e30f;
                        rA = fmaxf(rA, fmaxf(x0, x1));
                        rB = fmaxf(rB, fmaxf(x2, x3));
                    }
#pragma unroll
                    for (int o = 1; o <= 2; o <<= 1) {
                        rA = fmaxf(rA, __shfl_xor_sync(0xffffffffu, rA, o));
                        rB = fmaxf(rB, __shfl_xor_sync(0xffffffffu, rB, o));
                    }
                    if ((lane & 3) == 0) {
                        atomicMax(&rowmax[m0w + mt * 16 + g],     fenc(rA));
                        atomicMax(&rowmax[m0w + mt * 16 + 8 + g], fenc(rB));
                    }
                }
                // col maxes (max over this warp's 64 t rows = one b)
#pragma unroll
                for (int nt = 0; nt < 4; nt++) {
                    float cm0 = -1e30f, cm1 = -1e30f;
#pragma unroll
                    for (int mt = 0; mt < 4; mt++) {
                        cm0 = fmaxf(cm0, fmaxf(acc[mt][nt][0], acc[mt][nt][2]));
                        cm1 = fmaxf(cm1, fmaxf(acc[mt][nt][1], acc[mt][nt][3]));
                    }
#pragma unroll
                    for (int o = 4; o <= 16; o <<= 1) {
                        cm0 = fmaxf(cm0, __shfl_xor_sync(0xffffffffu, cm0, o));
                        cm1 = fmaxf(cm1, __shfl_xor_sync(0xffffffffu, cm1, o));
                    }
                    if (g == 0) {
                        const int v = vbase + nt * 8 + c2;
                        atomicMax(&colmax[mw * 224 + v],     fenc(cm0));
                        atomicMax(&colmax[mw * 224 + v + 1], fenc(cm1));
                    }
                }
            }
        }
        __syncthreads();
        buf ^= 1;
    }

    // final: warps 0..3 -> b 0..3 of the quad
    if (warp < 4) {
        const int bi = warp;
        float s1 = 0.f, s2 = 0.f;
        for (int i = lane; i < 64; i += 32)  s1 += fdec(rowmax[bi * 64 + i]);
        for (int i = lane; i < 196; i += 32) s2 += fdec(colmax[bi * 224 + i]);
#pragma unroll
        for (int o = 16; o; o >>= 1) {
            s1 += __shfl_xor_sync(0xffffffffu, s1, o);
            s2 += __shfl_xor_sync(0xffffffffu, s2, o);
        }
        if (lane == 0)
            sim[(4 * bq + bi) * 128 + q] = 0.5f * (s1 / 196.0f + s2 / 64.0f);
    }
}

// ---------------------------------------------------------------------------
extern "C" void kernel_launch(void* const* d_in, const int* in_sizes, int n_in,
                              void* d_out, int out_size) {
    const float* visual_cls     = (const float*)d_in[0];   // [128,768]
    const float* textual_cls    = (const float*)d_in[1];   // [128,768]
    const float* visual_tokens  = (const float*)d_in[2];   // [128,196,768]
    const float* textual_tokens = (const float*)d_in[3];   // [128,64,768]
    const float* Wv_cls = (const float*)d_in[4];
    const float* bv_cls = (const float*)d_in[5];
    const float* Wt_cls = (const float*)d_in[6];
    const float* bt_cls = (const float*)d_in[7];
    const float* Wv_tok = (const float*)d_in[8];
    const float* bv_tok = (const float*)d_in[9];
    const float* Wt_tok = (const float*)d_in[10];
    const float* bt_tok = (const float*)d_in[11];
    const int*   text_length = (const int*)d_in[12];

    float* out    = (float*)d_out;
    float* o_vcls = out;
    float* o_tcls = out + 65536;
    float* o_ve   = out + 131072;
    float* o_te   = out + 12976128;
    float* o_mask = out + 17170432;
    float* o_sim  = out + 17178624;

    __half *Ah, *Ar, *Wh;
    cudaGetSymbolAddress((void**)&Ah, g_Ah);
    cudaGetSymbolAddress((void**)&Ar, g_Ar);
    cudaGetSymbolAddress((void**)&Wh, g_Wh);

    const int WN4 = 512 * 768 / 4;

    // 0. fp32 -> fp16 h/r conversion (once; A reused 8x across N-blocks)
    convA_kernel<<<2048, 256>>>(visual_tokens, Ah, Ar, 25088 * 768 / 4);
    convA_kernel<<<2048, 256>>>(textual_tokens, Ah + (size_t)25088 * 768,
                                Ar + (size_t)25088 * 768, 8192 * 768 / 4);
    convA_kernel<<<96, 256>>>(visual_cls, Ah + (size_t)33280 * 768,
                              Ar + (size_t)33280 * 768, 128 * 768 / 4);
    convA_kernel<<<96, 256>>>(textual_cls, Ah + (size_t)33408 * 768,
                              Ar + (size_t)33408 * 768, 128 * 768 / 4);
    convW_kernel<<<384, 256>>>(Wv_tok, Wh + (size_t)0 * WN4 * 4, WN4);
    convW_kernel<<<384, 256>>>(Wt_tok, Wh + (size_t)1 * WN4 * 4, WN4);
    convW_kernel<<<384, 256>>>(Wv_cls, Wh + (size_t)2 * WN4 * 4, WN4);
    convW_kernel<<<384, 256>>>(Wt_cls, Wh + (size_t)3 * WN4 * 4, WN4);

    // 1. projections (pure-fp16, double-buffered cp.async)
    const int proj_smem = 2 * 3 * 64 * PKS * 2;  // 55,296 B
    cudaFuncSetAttribute(proj2_kernel, cudaFuncAttributeMaxDynamicSharedMemorySize,
                         proj_smem);
    proj2_kernel<<<dim3(392, 8), 256, proj_smem>>>(0,
        Wh + (size_t)0 * WN4 * 4, bv_tok, o_ve);
    proj2_kernel<<<dim3(128, 8), 256, proj_smem>>>(25088,
        Wh + (size_t)1 * WN4 * 4, bt_tok, o_te);
    proj2_kernel<<<dim3(2, 8), 256, proj_smem>>>(33280,
        Wh + (size_t)2 * WN4 * 4, bv_cls, o_vcls);
    proj2_kernel<<<dim3(2, 8), 256, proj_smem>>>(33408,
        Wh + (size_t)3 * WN4 * 4, bt_cls, o_tcls);

    // 2. L2 normalize (in place) + fp16 copies
    norm_kernel<<<3136, 256>>>(o_ve, 25088, 0);
    norm_kernel<<<1024, 256>>>(o_te, 8192, 1);

    // 3. text mask
    mask_kernel<<<32, 256>>>(text_length, o_mask);

    // 4. MaxSim v5 (M=256 b-quad CTAs, K-streamed, 64x32 warp tiles)
    const int maxsim_smem = (2 * 256 + 2 * 128) * KTS * 2 + (256 + 896) * 4; // 115,200 B
    cudaFuncSetAttribute(maxsim_kernel, cudaFuncAttributeMaxDynamicSharedMemorySize,
                         maxsim_smem);
    maxsim_kernel<<<dim3(128, 32), 512, maxsim_smem>>>(o_sim);
}

// round 16
// speedup vs baseline: 1.1812x; 1.1812x over previous
#include <cuda_runtime.h>
#include <cuda_fp16.h>
#include <cuda_bf16.h>

// ---------------------------------------------------------------------------
// SimpleFineGrainedHead4: B=128, Q=128, T=64, V=196, D=768, E=512
// Output layout (fp32, 17195008 elems):
//   [0]        visual_embed_cls  [128,512]
//   [65536]    textual_embed_cls [128,512]
//   [131072]   ve                [128,196,512]
//   [12976128] te                [128,64,512]
//   [17170432] text_mask         [128,64]
//   [17178624] sim               [128,128]
// NOTE: harness targets compute_103 (no 'a') -> tcgen05 unavailable; all
// tensor work via legacy mma.sync HMMA + cp.async.
// Lesson R12: maxsim needs 2 CTAs/SM for barrier overlap -- keep v3 tiling.
// ---------------------------------------------------------------------------

#define DEVFN __device__ __forceinline__

// fp16 copies of normalized ve/te for the MaxSim stage (device scratch).
__device__ __half g_ve_h[25088 * 512];
__device__ __half g_te_h[8192 * 512];

// fp16 copies of projection inputs (A: 33536 rows x 768) and weights.
// A row layout: [0,25088) visual_tokens, [25088,33280) textual_tokens,
//               [33280,33408) visual_cls, [33408,33536) textual_cls
__device__ __half g_Ah[33536 * 768];
// W layout: slot*512*768; slots: 0=Wv_tok 1=Wt_tok 2=Wv_cls 3=Wt_cls
__device__ __half g_Wh[4 * 512 * 768];

// ---------------- PTX helpers ----------------------------------------------
DEVFN unsigned smem_u32(const void* p) {
    return (unsigned)__cvta_generic_to_shared((void*)p);
}
DEVFN void ldsm4(unsigned& r0, unsigned& r1, unsigned& r2, unsigned& r3, const void* p) {
    unsigned a = smem_u32(p);
    asm volatile("ldmatrix.sync.aligned.m8n8.x4.shared.b16 {%0,%1,%2,%3}, [%4];\n"
                 : "=r"(r0), "=r"(r1), "=r"(r2), "=r"(r3) : "r"(a));
}
DEVFN void mma16816(float* c, unsigned a0, unsigned a1, unsigned a2, unsigned a3,
                    unsigned b0, unsigned b1) {
    asm volatile("mma.sync.aligned.m16n8k16.row.col.f32.f16.f16.f32 "
                 "{%0,%1,%2,%3}, {%4,%5,%6,%7}, {%8,%9}, {%0,%1,%2,%3};\n"
                 : "+f"(c[0]), "+f"(c[1]), "+f"(c[2]), "+f"(c[3])
                 : "r"(a0), "r"(a1), "r"(a2), "r"(a3), "r"(b0), "r"(b1));
}
DEVFN void cp16(void* dst, const void* src) {
    unsigned d = smem_u32(dst);
    asm volatile("cp.async.cg.shared.global [%0], [%1], 16;\n" :: "r"(d), "l"(src));
}
DEVFN void cp_commit() { asm volatile("cp.async.commit_group;\n"); }
DEVFN void cp_wait0()  { asm volatile("cp.async.wait_group 0;\n"); }
DEVFN void cp_wait1()  { asm volatile("cp.async.wait_group 1;\n"); }

// order-preserving float <-> uint encoding (for atomicMax on floats)
DEVFN unsigned fenc(float f) {
    unsigned u = __float_as_uint(f);
    return (u & 0x80000000u) ? ~u : (u | 0x80000000u);
}
DEVFN float fdec(unsigned u) {
    return __uint_as_float((u & 0x80000000u) ? (u & 0x7fffffffu) : ~u);
}

// ---------------------------------------------------------------------------
// Conversion kernel: fp32 -> fp16 (round-to-nearest). Used for A and W.
// ---------------------------------------------------------------------------
__global__ void __launch_bounds__(256) convH_kernel(
    const float* __restrict__ src, __half* __restrict__ h, int n4) {
    for (int i = blockIdx.x * blockDim.x + threadIdx.x; i < n4;
         i += gridDim.x * blockDim.x) {
        float4 v = ((const float4*)src)[i];
        float x[4] = {v.x, v.y, v.z, v.w};
        __half hb[4];
#pragma unroll
        for (int j = 0; j < 4; j++) hb[j] = __float2half_rn(x[j]);
        ((uint2*)h)[i] = *(const uint2*)hb;
    }
}

// ---------------------------------------------------------------------------
// Projection GEMM v3 (single-pass fp16 operands, fp32 accum):
//   C[M,512] = Ah[M,768] @ Wh[512,768]^T + bias
// Tile BM=64, BN=64, BK=64, double-buffered cp.async. 256 threads = 8 warps
// (4M x 2N), warp tile 16x32. grid = (M/64, 8).
// ---------------------------------------------------------------------------
#define PKS 72  // smem K stride (halves)

__global__ void __launch_bounds__(256) proj2_kernel(
    int a_row0, const __half* __restrict__ Wh,
    const float* __restrict__ bias, float* __restrict__ C) {
    extern __shared__ __align__(16) __half smp[];
    // layout: [2 buf][2 tile(Ah,Wh)][64][PKS]
    __half (*tl)[2][64][PKS] = (__half(*)[2][64][PKS])smp;

    const int tid = threadIdx.x, warp = tid >> 5, lane = tid & 31;
    const int m0 = (warp & 3) * 16, n0w = (warp >> 2) * 32;

    const __half* Ah_g = g_Ah + (size_t)(a_row0 + blockIdx.x * 64) * 768;
    const __half* Wh_g = Wh + (size_t)(blockIdx.y * 64) * 768;

    float acc[4][4];
#pragma unroll
    for (int i = 0; i < 4; i++)
#pragma unroll
        for (int j = 0; j < 4; j++) acc[i][j] = 0.f;

    for (int i = tid; i < 1024; i += 256) {
        int t = i >> 9, r = (i >> 3) & 63, c = (i & 7) * 8;
        const __half* src = (t == 0 ? Ah_g : Wh_g) + (size_t)r * 768 + c;
        cp16(&tl[0][t][r][c], src);
    }
    cp_commit();

    int buf = 0;
    for (int it = 0; it < 12; it++) {
        if (it < 11) {
            const int kb = (it + 1) * 64;
            const int ob = buf ^ 1;
            for (int i = tid; i < 1024; i += 256) {
                int t = i >> 9, r = (i >> 3) & 63, c = (i & 7) * 8;
                const __half* src = (t == 0 ? Ah_g : Wh_g) +
                                    (size_t)r * 768 + kb + c;
                cp16(&tl[ob][t][r][c], src);
            }
            cp_commit();
            cp_wait1();
        } else {
            cp_wait0();
        }
        __syncthreads();

        const int alo = lane & 15, ahi = (lane >> 4) << 3;
#pragma unroll
        for (int ks = 0; ks < 4; ks++) {
            const int kk = ks * 16;
            unsigned ah0, ah1, ah2, ah3;
            ldsm4(ah0, ah1, ah2, ah3, &tl[buf][0][m0 + alo][kk + ahi]);
#pragma unroll
            for (int ntp = 0; ntp < 2; ntp++) {
                unsigned bh0, bh1, bh2, bh3;
                ldsm4(bh0, bh1, bh2, bh3,
                      &tl[buf][1][n0w + ntp * 16 + alo][kk + ahi]);
                mma16816(acc[2 * ntp],     ah0, ah1, ah2, ah3, bh0, bh2);
                mma16816(acc[2 * ntp + 1], ah0, ah1, ah2, ah3, bh1, bh3);
            }
        }
        __syncthreads();
        buf ^= 1;
    }

    const int g = lane >> 2, c2 = (lane & 3) * 2;
    const size_t r0 = blockIdx.x * 64 + m0 + g;
#pragma unroll
    for (int nt = 0; nt < 4; nt++) {
        int col = blockIdx.y * 64 + n0w + nt * 8 + c2;
        float b0 = bias[col], b1 = bias[col + 1];
        C[r0 * 512 + col]           = acc[nt][0] + b0;
        C[r0 * 512 + col + 1]       = acc[nt][1] + b1;
        C[(r0 + 8) * 512 + col]     = acc[nt][2] + b0;
        C[(r0 + 8) * 512 + col + 1] = acc[nt][3] + b1;
    }
}

// ---------------------------------------------------------------------------
// Row-wise L2 normalize (rows of 512 fp32), in place; also write fp16 copy.
// ---------------------------------------------------------------------------
__global__ void __launch_bounds__(256) norm_kernel(float* __restrict__ data,
                                                   int rows, int which) {
    __half* hout = which ? g_te_h : g_ve_h;
    const int row = blockIdx.x * 8 + (threadIdx.x >> 5);
    const int lane = threadIdx.x & 31;
    if (row >= rows) return;
    float* p = data + (size_t)row * 512;

    float4 v[4];
    float s = 0.f;
#pragma unroll
    for (int i = 0; i < 4; i++) {
        v[i] = *(const float4*)(p + i * 128 + lane * 4);
        s += v[i].x * v[i].x + v[i].y * v[i].y + v[i].z * v[i].z + v[i].w * v[i].w;
    }
#pragma unroll
    for (int o = 16; o; o >>= 1) s += __shfl_xor_sync(0xffffffffu, s, o);
    float inv = 1.0f / fmaxf(sqrtf(s), 1e-12f);

    __half* hp = hout + (size_t)row * 512;
#pragma unroll
    for (int i = 0; i < 4; i++) {
        float4 w = v[i];
        w.x *= inv; w.y *= inv; w.z *= inv; w.w *= inv;
        *(float4*)(p + i * 128 + lane * 4) = w;
        __half h[4] = {__float2half_rn(w.x), __float2half_rn(w.y),
                       __float2half_rn(w.z), __float2half_rn(w.w)};
        *(uint2*)(hp + i * 128 + lane * 4) = *(const uint2*)h;
    }
}

// ---------------------------------------------------------------------------
// text_mask[b][t] = (t < text_length[b]); detects int64 vs int32 storage.
// ---------------------------------------------------------------------------
__global__ void mask_kernel(const int* __restrict__ tl, float* __restrict__ mask) {
    const bool is64 = (tl[1] == 0);
    for (int i = blockIdx.x * blockDim.x + threadIdx.x; i < 128 * 64;
         i += gridDim.x * blockDim.x) {
        int b = i >> 6, t = i & 63;
        int len = is64 ? tl[2 * b] : tl[b];
        mask[i] = (t < len) ? 1.0f : 0.0f;
    }
}

// ---------------------------------------------------------------------------
// MaxSim v3 (measured-best config). grid=(128 q, 64 b-pairs),
// 256 thr = 8 warps (2M x 4N), warp tile 64(M) x 32(N). te (128 rows = pair)
// and ve streamed through double-buffered K=64 smem tiles. V chunks {128, 96}
// (pad to 224; padded rows zeroed / masked). 2 CTAs/SM for barrier overlap.
// ---------------------------------------------------------------------------
#define KT  64   // K-tile halves
#define KTS 72   // smem K stride (halves)

__global__ void __launch_bounds__(256, 2) maxsim_kernel(float* __restrict__ sim) {
    const int q = blockIdx.x, bp = blockIdx.y;
    extern __shared__ char sm[];
    __half (*te_t)[128][KTS] = (__half(*)[128][KTS])sm;               // [2][128][KTS]
    __half (*ve_t)[128][KTS] = (__half(*)[128][KTS])(sm + 2 * 128 * KTS * 2);
    unsigned* rowmax = (unsigned*)(sm + 4 * 128 * KTS * 2);           // [128]
    unsigned* colmax = rowmax + 128;                                  // [2][224]

    const int tid = threadIdx.x, warp = tid >> 5, lane = tid & 31;
    const int mw = warp >> 2, nw = warp & 3;   // 2 M-warps x 4 N-warps
    const int m0w = mw * 64, n0w = nw * 32;
    const int lrow = lane & 15, lcol = (lane >> 4) << 3;

    for (int i = tid; i < 128 + 448; i += 256) rowmax[i] = 0u;

    const __half* teb = g_te_h + (size_t)bp * 128 * 512;
    const __half* veq = g_ve_h + (size_t)q * 196 * 512;

    // ---- preload (chunk0, kt0) into buf 0 ----
    {
        for (int i = tid; i < 1024; i += 256) {
            int r = i >> 3, c = (i & 7) * 8;
            cp16(&te_t[0][r][c], teb + (size_t)r * 512 + c);
        }
        for (int i = tid; i < 1024; i += 256) {
            int r = i >> 3, c = (i & 7) * 8;
            cp16(&ve_t[0][r][c], veq + (size_t)r * 512 + c);
        }
        cp_commit();
    }

    float acc[4][4][4];
    int buf = 0;

    for (int it = 0; it < 16; it++) {
        const int chunk = it >> 3, kt = it & 7;
        if (kt == 0) {
#pragma unroll
            for (int a = 0; a < 4; a++)
#pragma unroll
                for (int b = 0; b < 4; b++)
#pragma unroll
                    for (int c = 0; c < 4; c++) acc[a][b][c] = 0.f;
        }

        // prefetch next K-tile into the other buffer
        const int nit = it + 1;
        if (nit < 16) {
            const int nch = nit >> 3, nkt = nit & 7;
            const int kb = nkt * KT;
            const int ob = buf ^ 1;
            for (int i = tid; i < 1024; i += 256) {
                int r = i >> 3, c = (i & 7) * 8;
                cp16(&te_t[ob][r][c], teb + (size_t)r * 512 + kb + c);
            }
            const int nrows = nch ? 96 : 128;
            const int vb0 = nch * 128;
            for (int i = tid; i < nrows * 8; i += 256) {
                int r = i >> 3, c = (i & 7) * 8;
                int v = vb0 + r;
                if (v < 196) cp16(&ve_t[ob][r][c], veq + (size_t)v * 512 + kb + c);
                else *(uint4*)&ve_t[ob][r][c] = make_uint4(0, 0, 0, 0);
            }
            cp_commit();
            cp_wait1();
        } else {
            cp_wait0();
        }
        __syncthreads();

        const bool active = !(chunk == 1 && nw == 3);
        if (active) {
#pragma unroll
            for (int k0 = 0; k0 < KT; k0 += 16) {
                unsigned a[4][4];
#pragma unroll
                for (int mt = 0; mt < 4; mt++)
                    ldsm4(a[mt][0], a[mt][1], a[mt][2], a[mt][3],
                          &te_t[buf][m0w + mt * 16 + lrow][k0 + lcol]);
                unsigned bb[2][4];
#pragma unroll
                for (int np = 0; np < 2; np++)
                    ldsm4(bb[np][0], bb[np][1], bb[np][2], bb[np][3],
                          &ve_t[buf][n0w + np * 16 + lrow][k0 + lcol]);
#pragma unroll
                for (int mt = 0; mt < 4; mt++) {
                    mma16816(acc[mt][0], a[mt][0], a[mt][1], a[mt][2], a[mt][3],
                             bb[0][0], bb[0][2]);
                    mma16816(acc[mt][1], a[mt][0], a[mt][1], a[mt][2], a[mt][3],
                             bb[0][1], bb[0][3]);
                    mma16816(acc[mt][2], a[mt][0], a[mt][1], a[mt][2], a[mt][3],
                             bb[1][0], bb[1][2]);
                    mma16816(acc[mt][3], a[mt][0], a[mt][1], a[mt][2], a[mt][3],
                             bb[1][1], bb[1][3]);
                }
            }

            // ---- end-of-chunk reductions ----
            if (kt == 7) {
                const int g = lane >> 2, c2 = (lane & 3) * 2;
                const int vbase = chunk * 128 + n0w;
                // row maxes (max over this chunk's v), mask v >= 196
#pragma unroll
                for (int mt = 0; mt < 4; mt++) {
                    float rA = -1e30f, rB = -1e30f;
#pragma unroll
                    for (int nt = 0; nt < 4; nt++) {
                        const int vb = vbase + nt * 8 + c2;
                        float x0 = (vb < 196)     ? acc[mt][nt][0] : -1e30f;
                        float x1 = (vb + 1 < 196) ? acc[mt][nt][1] : -1e30f;
                        float x2 = (vb < 196)     ? acc[mt][nt][2] : -1e30f;
                        float x3 = (vb + 1 < 196) ? acc[mt][nt][3] : -1e30f;
                        rA = fmaxf(rA, fmaxf(x0, x1));
                        rB = fmaxf(rB, fmaxf(x2, x3));
                    }
#pragma unroll
                    for (int o = 1; o <= 2; o <<= 1) {
                        rA = fmaxf(rA, __shfl_xor_sync(0xffffffffu, rA, o));
                        rB = fmaxf(rB, __shfl_xor_sync(0xffffffffu, rB, o));
                    }
                    if ((lane & 3) == 0) {
                        atomicMax(&rowmax[m0w + mt * 16 + g],     fenc(rA));
                        atomicMax(&rowmax[m0w + mt * 16 + 8 + g], fenc(rB));
                    }
                }
                // col maxes (max over this warp's 64 t rows)
#pragma unroll
                for (int nt = 0; nt < 4; nt++) {
                    float cm0 = -1e30f, cm1 = -1e30f;
#pragma unroll
                    for (int mt = 0; mt < 4; mt++) {
                        cm0 = fmaxf(cm0, fmaxf(acc[mt][nt][0], acc[mt][nt][2]));
                        cm1 = fmaxf(cm1, fmaxf(acc[mt][nt][1], acc[mt][nt][3]));
                    }
#pragma unroll
                    for (int o = 4; o <= 16; o <<= 1) {
                        cm0 = fmaxf(cm0, __shfl_xor_sync(0xffffffffu, cm0, o));
                        cm1 = fmaxf(cm1, __shfl_xor_sync(0xffffffffu, cm1, o));
                    }
                    if (g == 0) {
                        const int v = vbase + nt * 8 + c2;
                        atomicMax(&colmax[mw * 224 + v],     fenc(cm0));
                        atomicMax(&colmax[mw * 224 + v + 1], fenc(cm1));
                    }
                }
            }
        }
        __syncthreads();
        buf ^= 1;
    }

    // final: warp 0 -> b0 of pair, warp 1 -> b1
    if (warp < 2) {
        const int bi = warp;
        float s1 = 0.f, s2 = 0.f;
        for (int i = lane; i < 64; i += 32)  s1 += fdec(rowmax[bi * 64 + i]);
        for (int i = lane; i < 196; i += 32) s2 += fdec(colmax[bi * 224 + i]);
#pragma unroll
        for (int o = 16; o; o >>= 1) {
            s1 += __shfl_xor_sync(0xffffffffu, s1, o);
            s2 += __shfl_xor_sync(0xffffffffu, s2, o);
        }
        if (lane == 0)
            sim[(2 * bp + bi) * 128 + q] = 0.5f * (s1 / 196.0f + s2 / 64.0f);
    }
}

// ---------------------------------------------------------------------------
extern "C" void kernel_launch(void* const* d_in, const int* in_sizes, int n_in,
                              void* d_out, int out_size) {
    const float* visual_cls     = (const float*)d_in[0];   // [128,768]
    const float* textual_cls    = (const float*)d_in[1];   // [128,768]
    const float* visual_tokens  = (const float*)d_in[2];   // [128,196,768]
    const float* textual_tokens = (const float*)d_in[3];   // [128,64,768]
    const float* Wv_cls = (const float*)d_in[4];
    const float* bv_cls = (const float*)d_in[5];
    const float* Wt_cls = (const float*)d_in[6];
    const float* bt_cls = (const float*)d_in[7];
    const float* Wv_tok = (const float*)d_in[8];
    const float* bv_tok = (const float*)d_in[9];
    const float* Wt_tok = (const float*)d_in[10];
    const float* bt_tok = (const float*)d_in[11];
    const int*   text_length = (const int*)d_in[12];

    float* out    = (float*)d_out;
    float* o_vcls = out;
    float* o_tcls = out + 65536;
    float* o_ve   = out + 131072;
    float* o_te   = out + 12976128;
    float* o_mask = out + 17170432;
    float* o_sim  = out + 17178624;

    __half *Ah, *Wh;
    cudaGetSymbolAddress((void**)&Ah, g_Ah);
    cudaGetSymbolAddress((void**)&Wh, g_Wh);

    const int WN4 = 512 * 768 / 4;

    // 0. fp32 -> fp16 conversion (single-pass; A reused 8x across N-blocks)
    convH_kernel<<<2048, 256>>>(visual_tokens, Ah, 25088 * 768 / 4);
    convH_kernel<<<2048, 256>>>(textual_tokens, Ah + (size_t)25088 * 768,
                                8192 * 768 / 4);
    convH_kernel<<<96, 256>>>(visual_cls, Ah + (size_t)33280 * 768,
                              128 * 768 / 4);
    convH_kernel<<<96, 256>>>(textual_cls, Ah + (size_t)33408 * 768,
                              128 * 768 / 4);
    convH_kernel<<<384, 256>>>(Wv_tok, Wh + (size_t)0 * WN4 * 4, WN4);
    convH_kernel<<<384, 256>>>(Wt_tok, Wh + (size_t)1 * WN4 * 4, WN4);
    convH_kernel<<<384, 256>>>(Wv_cls, Wh + (size_t)2 * WN4 * 4, WN4);
    convH_kernel<<<384, 256>>>(Wt_cls, Wh + (size_t)3 * WN4 * 4, WN4);

    // 1. projections (single-pass fp16, double-buffered cp.async)
    const int proj_smem = 2 * 2 * 64 * PKS * 2;  // 36,864 B
    cudaFuncSetAttribute(proj2_kernel, cudaFuncAttributeMaxDynamicSharedMemorySize,
                         proj_smem);
    proj2_kernel<<<dim3(392, 8), 256, proj_smem>>>(0,
        Wh + (size_t)0 * WN4 * 4, bv_tok, o_ve);
    proj2_kernel<<<dim3(128, 8), 256, proj_smem>>>(25088,
        Wh + (size_t)1 * WN4 * 4, bt_tok, o_te);
    proj2_kernel<<<dim3(2, 8), 256, proj_smem>>>(33280,
        Wh + (size_t)2 * WN4 * 4, bv_cls, o_vcls);
    proj2_kernel<<<dim3(2, 8), 256, proj_smem>>>(33408,
        Wh + (size_t)3 * WN4 * 4, bt_cls, o_tcls);

    // 2. L2 normalize (in place) + fp16 copies
    norm_kernel<<<3136, 256>>>(o_ve, 25088, 0);
    norm_kernel<<<1024, 256>>>(o_te, 8192, 1);

    // 3. text mask
    mask_kernel<<<32, 256>>>(text_length, o_mask);

    // 4. MaxSim v3 (b-pair CTAs, 2 CTAs/SM, K-streamed 64x32 tiles)
    const int maxsim_smem = 4 * 128 * KTS * 2 + (128 + 448) * 4;  // 76,032 B
    cudaFuncSetAttribute(maxsim_kernel, cudaFuncAttributeMaxDynamicSharedMemorySize,
                         maxsim_smem);
    maxsim_kernel<<<dim3(128, 64), 256, maxsim_smem>>>(o_sim);
}